// round 14
// baseline (speedup 1.0000x reference)
#include <cuda_runtime.h>
#include <cuda_fp16.h>
#include <cstdint>

#define NMAX 100000
#define EMAX 1600000
#define NCHUNK 4

// ---------------- device scratch (static: no allocation allowed) -------------
__device__ int    g_cnt[NMAX];
__device__ int    g_cursor[NMAX];
__device__ int    g_rowptr[NMAX];
__device__ float  g_dis[NMAX];
__device__ int    g_col[EMAX];
__device__ int    g_total;
__device__ __half g_buf0h[(size_t)NMAX * 128];  // gemm1 out UNscaled (agg1 gather src)
__device__ __half g_buf1h[(size_t)NMAX * 128];  // agg out (gemm input), both layers
__device__ __half g_buf2h[(size_t)NMAX * 128];  // gemm2 out prescaled (agg2 gather src)
__device__ __half g_buf3h[(size_t)NMAX * 16];   // gemm16 out prescaled (agg16 gather src)
__device__ __half g_wt1h[128 * 128];            // W1^T fp16 [n][k]
__device__ __half g_wt2h[128 * 128];            // W2^T fp16 [n][k]
__device__ __half g_wt3h[16 * 128];             // W3^T fp16 [n][k]

// ---------------- graph preprocessing ----------------------------------------
// init + W2/W3 transposes (W1^T is done on main, right before gemm1)
__global__ void initwt_k(int n, const float* __restrict__ W2,
                         const float* __restrict__ W3) {
    int i = blockIdx.x * blockDim.x + threadIdx.x;
    if (i < n) g_cnt[i] = 0;
    if (i == 0) g_total = 0;
    if (i < 128 * 128) {
        int nn = i >> 7, k = i & 127;
        g_wt2h[i] = __float2half(W2[k * 128 + nn]);
    }
    if (i < 16 * 128) {
        int nn = i >> 7, k = i & 127;
        g_wt3h[i] = __float2half(W3[k * 16 + nn]);
    }
}

// one-time: WT[n][k] = half(W[k][n]), 128x128 (runs on main before gemm1)
__global__ void wt1_k(const float* __restrict__ W, __half* __restrict__ WT) {
    int i = blockIdx.x * blockDim.x + threadIdx.x;
    int nn = i >> 7, k = i & 127;
    WT[nn * 128 + k] = __float2half(W[k * 128 + nn]);
}

__global__ void count_k(const int* __restrict__ dst, int e) {
    int i = blockIdx.x * blockDim.x + threadIdx.x;
    if (i < e) atomicAdd(&g_cnt[dst[i]], 1);
}

__global__ void dis_k(int n) {
    int i = blockIdx.x * blockDim.x + threadIdx.x;
    if (i < n) g_dis[i] = rsqrtf((float)(g_cnt[i] + 1));   // +1: self loop
}

// single-pass unordered segment allocation: rowptr[i] = atomic base + local scan.
__global__ void allocscan_k(int n) {
    __shared__ int s[512];
    __shared__ int base;
    int tid = threadIdx.x;
    int i = blockIdx.x * 512 + tid;
    int v = (i < n) ? g_cnt[i] : 0;
    s[tid] = v;
    __syncthreads();
    for (int off = 1; off < 512; off <<= 1) {
        int t = (tid >= off) ? s[tid - off] : 0;
        __syncthreads();
        s[tid] += t;
        __syncthreads();
    }
    if (tid == 511) base = atomicAdd(&g_total, s[511]);
    __syncthreads();
    if (i < n) {
        int rp = base + s[tid] - v;
        g_rowptr[i] = rp;
        g_cursor[i] = rp;
    }
}

__global__ void fill_k(const int* __restrict__ src, const int* __restrict__ dst, int e) {
    int i = blockIdx.x * blockDim.x + threadIdx.x;
    if (i < e) {
        int p = atomicAdd(&g_cursor[dst[i]], 1);
        g_col[p] = src[i];
    }
}

// ---------------- smem helpers ------------------------------------------------
__device__ __forceinline__ uint32_t smem_u32(const void* p) {
    return (uint32_t)__cvta_generic_to_shared(p);
}
__device__ __forceinline__ void ldsm_x4(uint32_t& r0, uint32_t& r1,
                                        uint32_t& r2, uint32_t& r3, uint32_t addr) {
    asm volatile("ldmatrix.sync.aligned.m8n8.x4.shared.b16 {%0,%1,%2,%3}, [%4];"
                 : "=r"(r0), "=r"(r1), "=r"(r2), "=r"(r3) : "r"(addr));
}

// ---------------- tensor-core GEMM: out = half([dis] * (A @ W)) --------------
// 128x128 blocktile, 8 warps, warp = 16 rows x 128 cols via m16n8k16 HMMA.
#define TS 136   // tile stride in halves; 68-word row shift -> LDSM conflict-free
template <bool A_FP32, bool SCALE>
__global__ __launch_bounds__(256)
void gemm128t_k(const void* __restrict__ Ain, const __half* __restrict__ WT,
                __half* __restrict__ out, int M, int roff) {
    __shared__ __half Ws[128 * TS];   // [n][k]
    __shared__ __half As[128 * TS];   // [row][k]
    const int t = threadIdx.x;
    const int w = t >> 5, l = t & 31;
    const int bm = blockIdx.x * 128;

    if (A_FP32) {
        const float* A = reinterpret_cast<const float*>(Ain);
#pragma unroll
        for (int i = 0; i < 16; i++) {
            int flat = t + 256 * i;
            int row  = flat >> 5;
            int c4   = (flat & 31) * 4;
            int gm   = bm + row;
            float4 f = make_float4(0.f, 0.f, 0.f, 0.f);
            if (gm < M) f = *reinterpret_cast<const float4*>(A + (size_t)gm * 128 + c4);
            __half2 h0 = __float22half2_rn(make_float2(f.x, f.y));
            __half2 h1 = __float22half2_rn(make_float2(f.z, f.w));
            uint2 packed;
            packed.x = *reinterpret_cast<uint32_t*>(&h0);
            packed.y = *reinterpret_cast<uint32_t*>(&h1);
            *reinterpret_cast<uint2*>(&As[row * TS + c4]) = packed;
        }
    } else {
        const __half* A = reinterpret_cast<const __half*>(Ain);
#pragma unroll
        for (int i = 0; i < 8; i++) {
            int flat = t + 256 * i;
            int row  = flat >> 4;
            int c8   = (flat & 15) * 8;
            int gm   = bm + row;
            uint4 v = make_uint4(0u, 0u, 0u, 0u);
            if (gm < M) v = *reinterpret_cast<const uint4*>(A + (size_t)gm * 128 + c8);
            *reinterpret_cast<uint4*>(&As[row * TS + c8]) = v;
        }
    }

#pragma unroll
    for (int i = 0; i < 8; i++) {
        int flat = t + 256 * i;
        int row  = flat >> 4;
        int c8   = (flat & 15) * 8;
        *reinterpret_cast<uint4*>(&Ws[row * TS + c8]) =
            *reinterpret_cast<const uint4*>(WT + row * 128 + c8);
    }

    __syncthreads();   // the only block sync

    float acc[16][4];
#pragma unroll
    for (int i = 0; i < 16; i++) {
        acc[i][0] = 0.f; acc[i][1] = 0.f; acc[i][2] = 0.f; acc[i][3] = 0.f;
    }

    const uint32_t a_base = smem_u32(As) +
        (uint32_t)(((w * 16 + (l & 15)) * TS + ((l >> 4) & 1) * 8) * 2);
    const uint32_t b_base = smem_u32(Ws) +
        (uint32_t)((((l & 7) + ((l >> 4) & 1) * 8) * TS + ((l >> 3) & 1) * 8) * 2);

#pragma unroll
    for (int kc = 0; kc < 8; kc++) {
        uint32_t a0, a1, a2, a3;
        ldsm_x4(a0, a1, a2, a3, a_base + (uint32_t)(kc * 32));
#pragma unroll
        for (int p = 0; p < 8; p++) {
            uint32_t b0, b1, b2, b3;
            ldsm_x4(b0, b1, b2, b3,
                    b_base + (uint32_t)(p * 16 * TS * 2 + kc * 32));
            asm volatile(
                "mma.sync.aligned.m16n8k16.row.col.f32.f16.f16.f32 "
                "{%0,%1,%2,%3}, {%4,%5,%6,%7}, {%8,%9}, {%0,%1,%2,%3};"
                : "+f"(acc[2 * p][0]), "+f"(acc[2 * p][1]),
                  "+f"(acc[2 * p][2]), "+f"(acc[2 * p][3])
                : "r"(a0), "r"(a1), "r"(a2), "r"(a3), "r"(b0), "r"(b1));
            asm volatile(
                "mma.sync.aligned.m16n8k16.row.col.f32.f16.f16.f32 "
                "{%0,%1,%2,%3}, {%4,%5,%6,%7}, {%8,%9}, {%0,%1,%2,%3};"
                : "+f"(acc[2 * p + 1][0]), "+f"(acc[2 * p + 1][1]),
                  "+f"(acc[2 * p + 1][2]), "+f"(acc[2 * p + 1][3])
                : "r"(a0), "r"(a1), "r"(a2), "r"(a3), "r"(b2), "r"(b3));
        }
    }

    const int mrow = w * 16 + (l >> 2);
    int r0 = bm + mrow;
    int r1 = r0 + 8;
    float d0 = 1.f, d1 = 1.f;
    if (SCALE) {
        d0 = (r0 < M) ? g_dis[r0 + roff] : 0.f;
        d1 = (r1 < M) ? g_dis[r1 + roff] : 0.f;
    }
#pragma unroll
    for (int nt = 0; nt < 16; nt++) {
        int col = nt * 8 + (l & 3) * 2;
        if (r0 < M)
            *reinterpret_cast<__half2*>(out + (size_t)r0 * 128 + col) =
                __float22half2_rn(make_float2(d0 * acc[nt][0], d0 * acc[nt][1]));
        if (r1 < M)
            *reinterpret_cast<__half2*>(out + (size_t)r1 * 128 + col) =
                __float22half2_rn(make_float2(d1 * acc[nt][2], d1 * acc[nt][3]));
    }
}

// ---------------- tensor-core GEMM small: Nout=16, fp16 out, prescaled -------
__global__ __launch_bounds__(256)
void gemm16t_k(const __half* __restrict__ A, const __half* __restrict__ WT,
               __half* __restrict__ out, int M, int roff) {
    __shared__ __half Ws[16 * TS];
    __shared__ __half As[128 * TS];
    const int t = threadIdx.x;
    const int w = t >> 5, l = t & 31;
    const int bm = blockIdx.x * 128;

#pragma unroll
    for (int i = 0; i < 8; i++) {
        int flat = t + 256 * i;
        int row  = flat >> 4;
        int c8   = (flat & 15) * 8;
        int gm   = bm + row;
        uint4 v = make_uint4(0u, 0u, 0u, 0u);
        if (gm < M) v = *reinterpret_cast<const uint4*>(A + (size_t)gm * 128 + c8);
        *reinterpret_cast<uint4*>(&As[row * TS + c8]) = v;
    }
    {
        int row = t >> 4;
        int c8  = (t & 15) * 8;
        *reinterpret_cast<uint4*>(&Ws[row * TS + c8]) =
            *reinterpret_cast<const uint4*>(WT + row * 128 + c8);
    }
    __syncthreads();

    float acc[2][4];
    acc[0][0] = acc[0][1] = acc[0][2] = acc[0][3] = 0.f;
    acc[1][0] = acc[1][1] = acc[1][2] = acc[1][3] = 0.f;

    const uint32_t a_base = smem_u32(As) +
        (uint32_t)(((w * 16 + (l & 15)) * TS + ((l >> 4) & 1) * 8) * 2);
    const uint32_t b_base = smem_u32(Ws) +
        (uint32_t)((((l & 7) + ((l >> 4) & 1) * 8) * TS + ((l >> 3) & 1) * 8) * 2);

#pragma unroll
    for (int kc = 0; kc < 8; kc++) {
        uint32_t a0, a1, a2, a3;
        ldsm_x4(a0, a1, a2, a3, a_base + (uint32_t)(kc * 32));
        uint32_t b0, b1, b2, b3;
        ldsm_x4(b0, b1, b2, b3, b_base + (uint32_t)(kc * 32));
        asm volatile(
            "mma.sync.aligned.m16n8k16.row.col.f32.f16.f16.f32 "
            "{%0,%1,%2,%3}, {%4,%5,%6,%7}, {%8,%9}, {%0,%1,%2,%3};"
            : "+f"(acc[0][0]), "+f"(acc[0][1]), "+f"(acc[0][2]), "+f"(acc[0][3])
            : "r"(a0), "r"(a1), "r"(a2), "r"(a3), "r"(b0), "r"(b1));
        asm volatile(
            "mma.sync.aligned.m16n8k16.row.col.f32.f16.f16.f32 "
            "{%0,%1,%2,%3}, {%4,%5,%6,%7}, {%8,%9}, {%0,%1,%2,%3};"
            : "+f"(acc[1][0]), "+f"(acc[1][1]), "+f"(acc[1][2]), "+f"(acc[1][3])
            : "r"(a0), "r"(a1), "r"(a2), "r"(a3), "r"(b2), "r"(b3));
    }

    const int mrow = w * 16 + (l >> 2);
    int r0 = bm + mrow;
    int r1 = r0 + 8;
    float d0 = (r0 < M) ? g_dis[r0 + roff] : 0.f;
    float d1 = (r1 < M) ? g_dis[r1 + roff] : 0.f;
#pragma unroll
    for (int nt = 0; nt < 2; nt++) {
        int col = nt * 8 + (l & 3) * 2;
        if (r0 < M)
            *reinterpret_cast<__half2*>(out + (size_t)r0 * 16 + col) =
                __float22half2_rn(make_float2(d0 * acc[nt][0], d0 * acc[nt][1]));
        if (r1 < M)
            *reinterpret_cast<__half2*>(out + (size_t)r1 * 16 + col) =
                __float22half2_rn(make_float2(d1 * acc[nt][2], d1 * acc[nt][3]));
    }
}

// ---------------- aggregation D=128, fp16 source, chunked --------------------
// EDGE_SCALE=0: source prescaled; out = relu(dis_d*(g_d + sum g_s) + b)
// EDGE_SCALE=1: source unscaled;  out = relu(dis_d*(dis_d*g_d + sum dis_s*g_s) + b)
template <int EDGE_SCALE>
__global__ __launch_bounds__(256)
void agg128h_k(const __half* __restrict__ g, const float* __restrict__ b,
               __half* __restrict__ outh, int n_off, int n_end, int relu) {
    int warp = n_off + ((blockIdx.x * blockDim.x + threadIdx.x) >> 5);
    int lane = threadIdx.x & 31;
    if (warp >= n_end) return;

    float dd = g_dis[warp];
    uint2 sraw = *reinterpret_cast<const uint2*>(g + (size_t)warp * 128 + lane * 4);
    float2 s0 = __half22float2(*reinterpret_cast<const __half2*>(&sraw.x));
    float2 s1 = __half22float2(*reinterpret_cast<const __half2*>(&sraw.y));
    float self_s = EDGE_SCALE ? dd : 1.f;
    float4 acc = make_float4(self_s * s0.x, self_s * s0.y, self_s * s1.x, self_s * s1.y);

    int start = g_rowptr[warp];
    int c     = g_cnt[warp];
    int i = 0;
    for (; i + 8 <= c; i += 8) {
        int s[8];
        float ds[8];
#pragma unroll
        for (int u = 0; u < 8; u++) s[u] = g_col[start + i + u];
        if (EDGE_SCALE) {
#pragma unroll
            for (int u = 0; u < 8; u++) ds[u] = g_dis[s[u]];
        }
#pragma unroll
        for (int u = 0; u < 8; u++) {
            uint2 raw = *reinterpret_cast<const uint2*>(g + (size_t)s[u] * 128 + lane * 4);
            float2 f0 = __half22float2(*reinterpret_cast<const __half2*>(&raw.x));
            float2 f1 = __half22float2(*reinterpret_cast<const __half2*>(&raw.y));
            if (EDGE_SCALE) {
                acc.x = fmaf(ds[u], f0.x, acc.x);
                acc.y = fmaf(ds[u], f0.y, acc.y);
                acc.z = fmaf(ds[u], f1.x, acc.z);
                acc.w = fmaf(ds[u], f1.y, acc.w);
            } else {
                acc.x += f0.x; acc.y += f0.y; acc.z += f1.x; acc.w += f1.y;
            }
        }
    }
    for (; i < c; i++) {
        int s = g_col[start + i];
        float ds = EDGE_SCALE ? g_dis[s] : 1.f;
        uint2 raw = *reinterpret_cast<const uint2*>(g + (size_t)s * 128 + lane * 4);
        float2 f0 = __half22float2(*reinterpret_cast<const __half2*>(&raw.x));
        float2 f1 = __half22float2(*reinterpret_cast<const __half2*>(&raw.y));
        acc.x = fmaf(ds, f0.x, acc.x);
        acc.y = fmaf(ds, f0.y, acc.y);
        acc.z = fmaf(ds, f1.x, acc.z);
        acc.w = fmaf(ds, f1.y, acc.w);
    }
    float4 bb = *reinterpret_cast<const float4*>(b + lane * 4);
    float4 r;
    r.x = fmaf(dd, acc.x, bb.x);
    r.y = fmaf(dd, acc.y, bb.y);
    r.z = fmaf(dd, acc.z, bb.z);
    r.w = fmaf(dd, acc.w, bb.w);
    if (relu) {
        r.x = fmaxf(r.x, 0.f); r.y = fmaxf(r.y, 0.f);
        r.z = fmaxf(r.z, 0.f); r.w = fmaxf(r.w, 0.f);
    }
    __half2 h0 = __float22half2_rn(make_float2(r.x, r.y));
    __half2 h1 = __float22half2_rn(make_float2(r.z, r.w));
    uint2 packed;
    packed.x = *reinterpret_cast<uint32_t*>(&h0);
    packed.y = *reinterpret_cast<uint32_t*>(&h1);
    *reinterpret_cast<uint2*>(outh + (size_t)warp * 128 + lane * 4) = packed;
}

// ---------------- aggregation D=16 over prescaled fp16 source, fp32 out ------
__global__ __launch_bounds__(256)
void agg16h_k(const __half* __restrict__ g, const float* __restrict__ b,
              float* __restrict__ out, int n) {
    int gt = blockIdx.x * blockDim.x + threadIdx.x;
    int node = gt >> 2, q = gt & 3;
    if (node >= n) return;
    uint2 sraw = *reinterpret_cast<const uint2*>(g + (size_t)node * 16 + q * 4);
    float2 s0 = __half22float2(*reinterpret_cast<const __half2*>(&sraw.x));
    float2 s1 = __half22float2(*reinterpret_cast<const __half2*>(&sraw.y));
    float4 acc = make_float4(s0.x, s0.y, s1.x, s1.y);
    int start = g_rowptr[node];
    int c     = g_cnt[node];
    for (int i = 0; i < c; i++) {
        int s = g_col[start + i];
        uint2 raw = *reinterpret_cast<const uint2*>(g + (size_t)s * 16 + q * 4);
        float2 f0 = __half22float2(*reinterpret_cast<const __half2*>(&raw.x));
        float2 f1 = __half22float2(*reinterpret_cast<const __half2*>(&raw.y));
        acc.x += f0.x; acc.y += f0.y; acc.z += f1.x; acc.w += f1.y;
    }
    float dd = g_dis[node];
    float4 bb = *reinterpret_cast<const float4*>(b + q * 4);
    float4 r;
    r.x = fmaf(dd, acc.x, bb.x);
    r.y = fmaf(dd, acc.y, bb.y);
    r.z = fmaf(dd, acc.z, bb.z);
    r.w = fmaf(dd, acc.w, bb.w);
    *reinterpret_cast<float4*>(out + (size_t)node * 16 + q * 4) = r;
}

// ---------------- launch ------------------------------------------------------
// main: wt1, gemm1 (unscaled, starts immediately)
// s2:   initwt(cnt=0, W2/W3^T), count, dis, allocscan, fill  (all under gemm1)
// then: agg1(edge-scaled, chunks) || gemm2(prescaled) on s2
//       agg2(chunks) || gemm16(prescaled) on s2 ; agg16 -> out
extern "C" void kernel_launch(void* const* d_in, const int* in_sizes, int n_in,
                              void* d_out, int out_size) {
    const float* x  = (const float*)d_in[0];
    const int*   ei = (const int*)d_in[1];
    const float* W1 = (const float*)d_in[2];
    const float* b1 = (const float*)d_in[3];
    const float* W2 = (const float*)d_in[4];
    const float* b2 = (const float*)d_in[5];
    const float* W3 = (const float*)d_in[6];
    const float* b3 = (const float*)d_in[7];
    float* out = (float*)d_out;

    int n = in_sizes[0] / 128;   // 100000
    int e = in_sizes[1] / 2;     // 1600000
    const int* src = ei;
    const int* dst = ei + e;

    __half *buf0h, *buf1h, *buf2h, *buf3h, *wt1h, *wt2h, *wt3h;
    cudaGetSymbolAddress((void**)&buf0h, g_buf0h);
    cudaGetSymbolAddress((void**)&buf1h, g_buf1h);
    cudaGetSymbolAddress((void**)&buf2h, g_buf2h);
    cudaGetSymbolAddress((void**)&buf3h, g_buf3h);
    cudaGetSymbolAddress((void**)&wt1h,  g_wt1h);
    cudaGetSymbolAddress((void**)&wt2h,  g_wt2h);
    cudaGetSymbolAddress((void**)&wt3h,  g_wt3h);

    static cudaStream_t s2 = nullptr;
    static cudaEvent_t ev_fork = nullptr, ev_csr = nullptr;
    static cudaEvent_t ev_a[NCHUNK], ev_g[NCHUNK], ev_b[NCHUNK], ev_h[NCHUNK];
    if (s2 == nullptr) {
        cudaStreamCreateWithFlags(&s2, cudaStreamNonBlocking);
        cudaEventCreateWithFlags(&ev_fork, cudaEventDisableTiming);
        cudaEventCreateWithFlags(&ev_csr,  cudaEventDisableTiming);
        for (int i = 0; i < NCHUNK; i++) {
            cudaEventCreateWithFlags(&ev_a[i], cudaEventDisableTiming);
            cudaEventCreateWithFlags(&ev_g[i], cudaEventDisableTiming);
            cudaEventCreateWithFlags(&ev_b[i], cudaEventDisableTiming);
            cudaEventCreateWithFlags(&ev_h[i], cudaEventDisableTiming);
        }
    }

    int chunk = (n + NCHUNK - 1) / NCHUNK;   // 25000

    cudaEventRecord(ev_fork, 0);
    cudaStreamWaitEvent(s2, ev_fork, 0);

    // Full CSR build on s2 — entirely concurrent with gemm1 on main.
    initwt_k   <<<(n + 255) / 256, 256, 0, s2>>>(n, W2, W3);
    count_k    <<<(e + 255) / 256, 256, 0, s2>>>(dst, e);
    dis_k      <<<(n + 255) / 256, 256, 0, s2>>>(n);
    allocscan_k<<<(n + 511) / 512, 512, 0, s2>>>(n);
    fill_k     <<<(e + 255) / 256, 256, 0, s2>>>(src, dst, e);
    cudaEventRecord(ev_csr, s2);

    // gemm1 on main: UNscaled (no dependency on CSR/dis)
    wt1_k<<<64, 256>>>(W1, wt1h);
    gemm128t_k<true, false><<<(n + 127) / 128, 256>>>(x, wt1h, buf0h, n, 0);

    cudaStreamWaitEvent(0, ev_csr, 0);   // agg needs CSR + dis

    // ---- agg1 (edge-scaled) chunks buf0h->buf1h; gemm2 chunks buf1h->buf2h on s2
    for (int i = 0; i < NCHUNK; i++) {
        int off = i * chunk;
        int end = (off + chunk < n) ? off + chunk : n;
        int cnt = end - off;
        agg128h_k<1><<<(cnt * 32 + 255) / 256, 256>>>(buf0h, b1, buf1h, off, end, 1);
        cudaEventRecord(ev_a[i], 0);
        cudaStreamWaitEvent(s2, ev_a[i], 0);
        gemm128t_k<false, true><<<(cnt + 127) / 128, 256, 0, s2>>>(
            buf1h + (size_t)off * 128, wt2h, buf2h + (size_t)off * 128, cnt, off);
        cudaEventRecord(ev_g[i], s2);
    }
    for (int i = 0; i < NCHUNK; i++) cudaStreamWaitEvent(0, ev_g[i], 0);

    // ---- agg2 chunks buf2h->buf1h; gemm16 chunks buf1h->buf3h on s2
    for (int i = 0; i < NCHUNK; i++) {
        int off = i * chunk;
        int end = (off + chunk < n) ? off + chunk : n;
        int cnt = end - off;
        agg128h_k<0><<<(cnt * 32 + 255) / 256, 256>>>(buf2h, b2, buf1h, off, end, 1);
        cudaEventRecord(ev_b[i], 0);
        cudaStreamWaitEvent(s2, ev_b[i], 0);
        gemm16t_k<<<(cnt + 127) / 128, 256, 0, s2>>>(
            buf1h + (size_t)off * 128, wt3h, buf3h + (size_t)off * 16, cnt, off);
        cudaEventRecord(ev_h[i], s2);
    }
    for (int i = 0; i < NCHUNK; i++) cudaStreamWaitEvent(0, ev_h[i], 0);

    agg16h_k<<<(n * 4 + 255) / 256, 256>>>(buf3h, b3, out, n);
}

// round 15
// speedup vs baseline: 1.1340x; 1.1340x over previous
#include <cuda_runtime.h>
#include <cuda_fp16.h>
#include <cstdint>

#define NMAX 100000
#define EMAX 1600000
#define NCHUNK 2

// ---------------- device scratch (static: no allocation allowed) -------------
__device__ int    g_cnt[NMAX];
__device__ int    g_cursor[NMAX];
__device__ int    g_rowptr[NMAX];
__device__ float  g_dis[NMAX];
__device__ int    g_col[EMAX];
__device__ int    g_total;
__device__ __half g_buf0h[(size_t)NMAX * 128];  // gemm1 out prescaled (agg1 gather src)
__device__ __half g_buf1h[(size_t)NMAX * 128];  // agg out (gemm input), both layers
__device__ __half g_buf2h[(size_t)NMAX * 128];  // gemm2 out prescaled (agg2 gather src)
__device__ __half g_buf3h[(size_t)NMAX * 16];   // gemm16 out prescaled (agg16 gather src)
__device__ __half g_wt1h[128 * 128];            // W1^T fp16 [n][k]
__device__ __half g_wt2h[128 * 128];            // W2^T fp16 [n][k]
__device__ __half g_wt3h[16 * 128];             // W3^T fp16 [n][k]

// ---------------- graph preprocessing ----------------------------------------
__global__ void init_k(int n) {
    int i = blockIdx.x * blockDim.x + threadIdx.x;
    if (i < n) g_cnt[i] = 0;
    if (i == 0) g_total = 0;
}

__global__ void count_k(const int* __restrict__ dst, int e) {
    int i = blockIdx.x * blockDim.x + threadIdx.x;
    if (i < e) atomicAdd(&g_cnt[dst[i]], 1);
}

__global__ void dis_k(int n) {
    int i = blockIdx.x * blockDim.x + threadIdx.x;
    if (i < n) g_dis[i] = rsqrtf((float)(g_cnt[i] + 1));   // +1: self loop
}

// all three weight transposes, on main while it waits for count
__global__ void wtall_k(const float* __restrict__ W1, const float* __restrict__ W2,
                        const float* __restrict__ W3) {
    int i = blockIdx.x * blockDim.x + threadIdx.x;
    if (i < 128 * 128) {
        int nn = i >> 7, k = i & 127;
        g_wt1h[i] = __float2half(W1[k * 128 + nn]);
        g_wt2h[i] = __float2half(W2[k * 128 + nn]);
    }
    if (i < 16 * 128) {
        int nn = i >> 7, k = i & 127;
        g_wt3h[i] = __float2half(W3[k * 16 + nn]);
    }
}

// single-pass unordered segment allocation: rowptr[i] = atomic base + local scan.
__global__ void allocscan_k(int n) {
    __shared__ int s[512];
    __shared__ int base;
    int tid = threadIdx.x;
    int i = blockIdx.x * 512 + tid;
    int v = (i < n) ? g_cnt[i] : 0;
    s[tid] = v;
    __syncthreads();
    for (int off = 1; off < 512; off <<= 1) {
        int t = (tid >= off) ? s[tid - off] : 0;
        __syncthreads();
        s[tid] += t;
        __syncthreads();
    }
    if (tid == 511) base = atomicAdd(&g_total, s[511]);
    __syncthreads();
    if (i < n) {
        int rp = base + s[tid] - v;
        g_rowptr[i] = rp;
        g_cursor[i] = rp;
    }
}

__global__ void fill_k(const int* __restrict__ src, const int* __restrict__ dst, int e) {
    int i = blockIdx.x * blockDim.x + threadIdx.x;
    if (i < e) {
        int p = atomicAdd(&g_cursor[dst[i]], 1);
        g_col[p] = src[i];
    }
}

// ---------------- smem helpers ------------------------------------------------
__device__ __forceinline__ uint32_t smem_u32(const void* p) {
    return (uint32_t)__cvta_generic_to_shared(p);
}
__device__ __forceinline__ void ldsm_x4(uint32_t& r0, uint32_t& r1,
                                        uint32_t& r2, uint32_t& r3, uint32_t addr) {
    asm volatile("ldmatrix.sync.aligned.m8n8.x4.shared.b16 {%0,%1,%2,%3}, [%4];"
                 : "=r"(r0), "=r"(r1), "=r"(r2), "=r"(r3) : "r"(addr));
}

// ---------------- tensor-core GEMM: out = half(dis * (A @ W)) ----------------
// 128x128 blocktile, 8 warps, warp = 16 rows x 128 cols via m16n8k16 HMMA.
// SCALE_FROM_CNT: scale = rsqrt(cnt+1) computed in epilogue (no dep on dis_k).
#define TS 136   // tile stride in halves; 68-word row shift -> LDSM conflict-free
template <bool A_FP32, bool SCALE_FROM_CNT>
__global__ __launch_bounds__(256)
void gemm128t_k(const void* __restrict__ Ain, const __half* __restrict__ WT,
                __half* __restrict__ out, int M, int roff) {
    __shared__ __half Ws[128 * TS];   // [n][k]
    __shared__ __half As[128 * TS];   // [row][k]
    const int t = threadIdx.x;
    const int w = t >> 5, l = t & 31;
    const int bm = blockIdx.x * 128;

    if (A_FP32) {
        const float* A = reinterpret_cast<const float*>(Ain);
#pragma unroll
        for (int i = 0; i < 16; i++) {
            int flat = t + 256 * i;
            int row  = flat >> 5;
            int c4   = (flat & 31) * 4;
            int gm   = bm + row;
            float4 f = make_float4(0.f, 0.f, 0.f, 0.f);
            if (gm < M) f = *reinterpret_cast<const float4*>(A + (size_t)gm * 128 + c4);
            __half2 h0 = __float22half2_rn(make_float2(f.x, f.y));
            __half2 h1 = __float22half2_rn(make_float2(f.z, f.w));
            uint2 packed;
            packed.x = *reinterpret_cast<uint32_t*>(&h0);
            packed.y = *reinterpret_cast<uint32_t*>(&h1);
            *reinterpret_cast<uint2*>(&As[row * TS + c4]) = packed;
        }
    } else {
        const __half* A = reinterpret_cast<const __half*>(Ain);
#pragma unroll
        for (int i = 0; i < 8; i++) {
            int flat = t + 256 * i;
            int row  = flat >> 4;
            int c8   = (flat & 15) * 8;
            int gm   = bm + row;
            uint4 v = make_uint4(0u, 0u, 0u, 0u);
            if (gm < M) v = *reinterpret_cast<const uint4*>(A + (size_t)gm * 128 + c8);
            *reinterpret_cast<uint4*>(&As[row * TS + c8]) = v;
        }
    }

#pragma unroll
    for (int i = 0; i < 8; i++) {
        int flat = t + 256 * i;
        int row  = flat >> 4;
        int c8   = (flat & 15) * 8;
        *reinterpret_cast<uint4*>(&Ws[row * TS + c8]) =
            *reinterpret_cast<const uint4*>(WT + row * 128 + c8);
    }

    __syncthreads();   // the only block sync

    float acc[16][4];
#pragma unroll
    for (int i = 0; i < 16; i++) {
        acc[i][0] = 0.f; acc[i][1] = 0.f; acc[i][2] = 0.f; acc[i][3] = 0.f;
    }

    const uint32_t a_base = smem_u32(As) +
        (uint32_t)(((w * 16 + (l & 15)) * TS + ((l >> 4) & 1) * 8) * 2);
    const uint32_t b_base = smem_u32(Ws) +
        (uint32_t)((((l & 7) + ((l >> 4) & 1) * 8) * TS + ((l >> 3) & 1) * 8) * 2);

#pragma unroll
    for (int kc = 0; kc < 8; kc++) {
        uint32_t a0, a1, a2, a3;
        ldsm_x4(a0, a1, a2, a3, a_base + (uint32_t)(kc * 32));
#pragma unroll
        for (int p = 0; p < 8; p++) {
            uint32_t b0, b1, b2, b3;
            ldsm_x4(b0, b1, b2, b3,
                    b_base + (uint32_t)(p * 16 * TS * 2 + kc * 32));
            asm volatile(
                "mma.sync.aligned.m16n8k16.row.col.f32.f16.f16.f32 "
                "{%0,%1,%2,%3}, {%4,%5,%6,%7}, {%8,%9}, {%0,%1,%2,%3};"
                : "+f"(acc[2 * p][0]), "+f"(acc[2 * p][1]),
                  "+f"(acc[2 * p][2]), "+f"(acc[2 * p][3])
                : "r"(a0), "r"(a1), "r"(a2), "r"(a3), "r"(b0), "r"(b1));
            asm volatile(
                "mma.sync.aligned.m16n8k16.row.col.f32.f16.f16.f32 "
                "{%0,%1,%2,%3}, {%4,%5,%6,%7}, {%8,%9}, {%0,%1,%2,%3};"
                : "+f"(acc[2 * p + 1][0]), "+f"(acc[2 * p + 1][1]),
                  "+f"(acc[2 * p + 1][2]), "+f"(acc[2 * p + 1][3])
                : "r"(a0), "r"(a1), "r"(a2), "r"(a3), "r"(b2), "r"(b3));
        }
    }

    const int mrow = w * 16 + (l >> 2);
    int r0 = bm + mrow;
    int r1 = r0 + 8;
    float d0, d1;
    if (SCALE_FROM_CNT) {
        d0 = (r0 < M) ? rsqrtf((float)(g_cnt[r0 + roff] + 1)) : 0.f;
        d1 = (r1 < M) ? rsqrtf((float)(g_cnt[r1 + roff] + 1)) : 0.f;
    } else {
        d0 = (r0 < M) ? g_dis[r0 + roff] : 0.f;
        d1 = (r1 < M) ? g_dis[r1 + roff] : 0.f;
    }
#pragma unroll
    for (int nt = 0; nt < 16; nt++) {
        int col = nt * 8 + (l & 3) * 2;
        if (r0 < M)
            *reinterpret_cast<__half2*>(out + (size_t)r0 * 128 + col) =
                __float22half2_rn(make_float2(d0 * acc[nt][0], d0 * acc[nt][1]));
        if (r1 < M)
            *reinterpret_cast<__half2*>(out + (size_t)r1 * 128 + col) =
                __float22half2_rn(make_float2(d1 * acc[nt][2], d1 * acc[nt][3]));
    }
}

// ---------------- tensor-core GEMM small: Nout=16, fp16 out, prescaled -------
__global__ __launch_bounds__(256)
void gemm16t_k(const __half* __restrict__ A, const __half* __restrict__ WT,
               __half* __restrict__ out, int M, int roff) {
    __shared__ __half Ws[16 * TS];
    __shared__ __half As[128 * TS];
    const int t = threadIdx.x;
    const int w = t >> 5, l = t & 31;
    const int bm = blockIdx.x * 128;

#pragma unroll
    for (int i = 0; i < 8; i++) {
        int flat = t + 256 * i;
        int row  = flat >> 4;
        int c8   = (flat & 15) * 8;
        int gm   = bm + row;
        uint4 v = make_uint4(0u, 0u, 0u, 0u);
        if (gm < M) v = *reinterpret_cast<const uint4*>(A + (size_t)gm * 128 + c8);
        *reinterpret_cast<uint4*>(&As[row * TS + c8]) = v;
    }
    {
        int row = t >> 4;
        int c8  = (t & 15) * 8;
        *reinterpret_cast<uint4*>(&Ws[row * TS + c8]) =
            *reinterpret_cast<const uint4*>(WT + row * 128 + c8);
    }
    __syncthreads();

    float acc[2][4];
    acc[0][0] = acc[0][1] = acc[0][2] = acc[0][3] = 0.f;
    acc[1][0] = acc[1][1] = acc[1][2] = acc[1][3] = 0.f;

    const uint32_t a_base = smem_u32(As) +
        (uint32_t)(((w * 16 + (l & 15)) * TS + ((l >> 4) & 1) * 8) * 2);
    const uint32_t b_base = smem_u32(Ws) +
        (uint32_t)((((l & 7) + ((l >> 4) & 1) * 8) * TS + ((l >> 3) & 1) * 8) * 2);

#pragma unroll
    for (int kc = 0; kc < 8; kc++) {
        uint32_t a0, a1, a2, a3;
        ldsm_x4(a0, a1, a2, a3, a_base + (uint32_t)(kc * 32));
        uint32_t b0, b1, b2, b3;
        ldsm_x4(b0, b1, b2, b3, b_base + (uint32_t)(kc * 32));
        asm volatile(
            "mma.sync.aligned.m16n8k16.row.col.f32.f16.f16.f32 "
            "{%0,%1,%2,%3}, {%4,%5,%6,%7}, {%8,%9}, {%0,%1,%2,%3};"
            : "+f"(acc[0][0]), "+f"(acc[0][1]), "+f"(acc[0][2]), "+f"(acc[0][3])
            : "r"(a0), "r"(a1), "r"(a2), "r"(a3), "r"(b0), "r"(b1));
        asm volatile(
            "mma.sync.aligned.m16n8k16.row.col.f32.f16.f16.f32 "
            "{%0,%1,%2,%3}, {%4,%5,%6,%7}, {%8,%9}, {%0,%1,%2,%3};"
            : "+f"(acc[1][0]), "+f"(acc[1][1]), "+f"(acc[1][2]), "+f"(acc[1][3])
            : "r"(a0), "r"(a1), "r"(a2), "r"(a3), "r"(b2), "r"(b3));
    }

    const int mrow = w * 16 + (l >> 2);
    int r0 = bm + mrow;
    int r1 = r0 + 8;
    float d0 = (r0 < M) ? g_dis[r0 + roff] : 0.f;
    float d1 = (r1 < M) ? g_dis[r1 + roff] : 0.f;
#pragma unroll
    for (int nt = 0; nt < 2; nt++) {
        int col = nt * 8 + (l & 3) * 2;
        if (r0 < M)
            *reinterpret_cast<__half2*>(out + (size_t)r0 * 16 + col) =
                __float22half2_rn(make_float2(d0 * acc[nt][0], d0 * acc[nt][1]));
        if (r1 < M)
            *reinterpret_cast<__half2*>(out + (size_t)r1 * 16 + col) =
                __float22half2_rn(make_float2(d1 * acc[nt][2], d1 * acc[nt][3]));
    }
}

// ---------------- aggregation D=128, prescaled fp16 source, chunked ----------
__global__ __launch_bounds__(256)
void agg128h_k(const __half* __restrict__ g, const float* __restrict__ b,
               __half* __restrict__ outh, int n_off, int n_end, int relu) {
    int warp = n_off + ((blockIdx.x * blockDim.x + threadIdx.x) >> 5);
    int lane = threadIdx.x & 31;
    if (warp >= n_end) return;

    uint2 sraw = *reinterpret_cast<const uint2*>(g + (size_t)warp * 128 + lane * 4);
    float2 s0 = __half22float2(*reinterpret_cast<const __half2*>(&sraw.x));
    float2 s1 = __half22float2(*reinterpret_cast<const __half2*>(&sraw.y));
    float4 acc = make_float4(s0.x, s0.y, s1.x, s1.y);

    int start = g_rowptr[warp];
    int c     = g_cnt[warp];
    int i = 0;
    for (; i + 8 <= c; i += 8) {
        int s[8];
#pragma unroll
        for (int u = 0; u < 8; u++) s[u] = g_col[start + i + u];
#pragma unroll
        for (int u = 0; u < 8; u++) {
            uint2 raw = *reinterpret_cast<const uint2*>(g + (size_t)s[u] * 128 + lane * 4);
            float2 f0 = __half22float2(*reinterpret_cast<const __half2*>(&raw.x));
            float2 f1 = __half22float2(*reinterpret_cast<const __half2*>(&raw.y));
            acc.x += f0.x; acc.y += f0.y; acc.z += f1.x; acc.w += f1.y;
        }
    }
    for (; i < c; i++) {
        int s = g_col[start + i];
        uint2 raw = *reinterpret_cast<const uint2*>(g + (size_t)s * 128 + lane * 4);
        float2 f0 = __half22float2(*reinterpret_cast<const __half2*>(&raw.x));
        float2 f1 = __half22float2(*reinterpret_cast<const __half2*>(&raw.y));
        acc.x += f0.x; acc.y += f0.y; acc.z += f1.x; acc.w += f1.y;
    }
    float dd = g_dis[warp];
    float4 bb = *reinterpret_cast<const float4*>(b + lane * 4);
    float4 r;
    r.x = fmaf(dd, acc.x, bb.x);
    r.y = fmaf(dd, acc.y, bb.y);
    r.z = fmaf(dd, acc.z, bb.z);
    r.w = fmaf(dd, acc.w, bb.w);
    if (relu) {
        r.x = fmaxf(r.x, 0.f); r.y = fmaxf(r.y, 0.f);
        r.z = fmaxf(r.z, 0.f); r.w = fmaxf(r.w, 0.f);
    }
    __half2 h0 = __float22half2_rn(make_float2(r.x, r.y));
    __half2 h1 = __float22half2_rn(make_float2(r.z, r.w));
    uint2 packed;
    packed.x = *reinterpret_cast<uint32_t*>(&h0);
    packed.y = *reinterpret_cast<uint32_t*>(&h1);
    *reinterpret_cast<uint2*>(outh + (size_t)warp * 128 + lane * 4) = packed;
}

// ---------------- aggregation D=16 over prescaled fp16 source, fp32 out ------
__global__ __launch_bounds__(256)
void agg16h_k(const __half* __restrict__ g, const float* __restrict__ b,
              float* __restrict__ out, int n) {
    int gt = blockIdx.x * blockDim.x + threadIdx.x;
    int node = gt >> 2, q = gt & 3;
    if (node >= n) return;
    uint2 sraw = *reinterpret_cast<const uint2*>(g + (size_t)node * 16 + q * 4);
    float2 s0 = __half22float2(*reinterpret_cast<const __half2*>(&sraw.x));
    float2 s1 = __half22float2(*reinterpret_cast<const __half2*>(&sraw.y));
    float4 acc = make_float4(s0.x, s0.y, s1.x, s1.y);
    int start = g_rowptr[node];
    int c     = g_cnt[node];
    for (int i = 0; i < c; i++) {
        int s = g_col[start + i];
        uint2 raw = *reinterpret_cast<const uint2*>(g + (size_t)s * 16 + q * 4);
        float2 f0 = __half22float2(*reinterpret_cast<const __half2*>(&raw.x));
        float2 f1 = __half22float2(*reinterpret_cast<const __half2*>(&raw.y));
        acc.x += f0.x; acc.y += f0.y; acc.z += f1.x; acc.w += f1.y;
    }
    float dd = g_dis[node];
    float4 bb = *reinterpret_cast<const float4*>(b + q * 4);
    float4 r;
    r.x = fmaf(dd, acc.x, bb.x);
    r.y = fmaf(dd, acc.y, bb.y);
    r.z = fmaf(dd, acc.z, bb.z);
    r.w = fmaf(dd, acc.w, bb.w);
    *reinterpret_cast<float4*>(out + (size_t)node * 16 + q * 4) = r;
}

// ---------------- launch ------------------------------------------------------
// s2:   init, count [ev_cnt] ; dis, allocscan, fill [ev_csr] (latter under gemm1)
// main: wtall (during count wait), gemm1 (scale from cnt)
// then: agg1 (uneven chunks) || gemm2 on s2 ; agg2 || gemm16 on s2 ; agg16
extern "C" void kernel_launch(void* const* d_in, const int* in_sizes, int n_in,
                              void* d_out, int out_size) {
    const float* x  = (const float*)d_in[0];
    const int*   ei = (const int*)d_in[1];
    const float* W1 = (const float*)d_in[2];
    const float* b1 = (const float*)d_in[3];
    const float* W2 = (const float*)d_in[4];
    const float* b2 = (const float*)d_in[5];
    const float* W3 = (const float*)d_in[6];
    const float* b3 = (const float*)d_in[7];
    float* out = (float*)d_out;

    int n = in_sizes[0] / 128;   // 100000
    int e = in_sizes[1] / 2;     // 1600000
    const int* src = ei;
    const int* dst = ei + e;

    __half *buf0h, *buf1h, *buf2h, *buf3h, *wt1h, *wt2h, *wt3h;
    cudaGetSymbolAddress((void**)&buf0h, g_buf0h);
    cudaGetSymbolAddress((void**)&buf1h, g_buf1h);
    cudaGetSymbolAddress((void**)&buf2h, g_buf2h);
    cudaGetSymbolAddress((void**)&buf3h, g_buf3h);
    cudaGetSymbolAddress((void**)&wt1h,  g_wt1h);
    cudaGetSymbolAddress((void**)&wt2h,  g_wt2h);
    cudaGetSymbolAddress((void**)&wt3h,  g_wt3h);

    static cudaStream_t s2 = nullptr;
    static cudaEvent_t ev_fork = nullptr, ev_cnt = nullptr, ev_csr = nullptr;
    static cudaEvent_t ev_a[NCHUNK], ev_g[NCHUNK], ev_b[NCHUNK], ev_h[NCHUNK];
    if (s2 == nullptr) {
        cudaStreamCreateWithFlags(&s2, cudaStreamNonBlocking);
        cudaEventCreateWithFlags(&ev_fork, cudaEventDisableTiming);
        cudaEventCreateWithFlags(&ev_cnt,  cudaEventDisableTiming);
        cudaEventCreateWithFlags(&ev_csr,  cudaEventDisableTiming);
        for (int i = 0; i < NCHUNK; i++) {
            cudaEventCreateWithFlags(&ev_a[i], cudaEventDisableTiming);
            cudaEventCreateWithFlags(&ev_g[i], cudaEventDisableTiming);
            cudaEventCreateWithFlags(&ev_b[i], cudaEventDisableTiming);
            cudaEventCreateWithFlags(&ev_h[i], cudaEventDisableTiming);
        }
    }

    // uneven chunks: 64% / 36% (smaller tail => less exposed gemm)
    int c0 = ((n * 16) / 25 + 127) & ~127;   // 64000
    int offs[NCHUNK + 1] = {0, c0, n};

    cudaEventRecord(ev_fork, 0);
    cudaStreamWaitEvent(s2, ev_fork, 0);

    // prefix on s2: init -> count (gemm1's epilogue reads g_cnt directly)
    init_k <<<(n + 255) / 256, 256, 0, s2>>>(n);
    count_k<<<(e + 255) / 256, 256, 0, s2>>>(dst, e);
    cudaEventRecord(ev_cnt, s2);

    // weight transposes on main while count runs
    wtall_k<<<64, 256>>>(W1, W2, W3);

    cudaStreamWaitEvent(0, ev_cnt, 0);
    gemm128t_k<true, true><<<(n + 127) / 128, 256>>>(x, wt1h, buf0h, n, 0);

    // rest of CSR on s2, under gemm1
    dis_k      <<<(n + 255) / 256, 256, 0, s2>>>(n);
    allocscan_k<<<(n + 511) / 512, 512, 0, s2>>>(n);
    fill_k     <<<(e + 255) / 256, 256, 0, s2>>>(src, dst, e);
    cudaEventRecord(ev_csr, s2);
    cudaStreamWaitEvent(0, ev_csr, 0);   // agg needs CSR + dis

    // ---- agg1 chunks buf0h->buf1h; gemm2 chunks buf1h->buf2h on s2
    for (int i = 0; i < NCHUNK; i++) {
        int off = offs[i], end = offs[i + 1], cnt = end - off;
        agg128h_k<<<(cnt * 32 + 255) / 256, 256>>>(buf0h, b1, buf1h, off, end, 1);
        cudaEventRecord(ev_a[i], 0);
        cudaStreamWaitEvent(s2, ev_a[i], 0);
        gemm128t_k<false, false><<<(cnt + 127) / 128, 256, 0, s2>>>(
            buf1h + (size_t)off * 128, wt2h, buf2h + (size_t)off * 128, cnt, off);
        cudaEventRecord(ev_g[i], s2);
    }
    for (int i = 0; i < NCHUNK; i++) cudaStreamWaitEvent(0, ev_g[i], 0);

    // ---- agg2 chunks buf2h->buf1h; gemm16 chunks buf1h->buf3h on s2
    for (int i = 0; i < NCHUNK; i++) {
        int off = offs[i], end = offs[i + 1], cnt = end - off;
        agg128h_k<<<(cnt * 32 + 255) / 256, 256>>>(buf2h, b2, buf1h, off, end, 1);
        cudaEventRecord(ev_b[i], 0);
        cudaStreamWaitEvent(s2, ev_b[i], 0);
        gemm16t_k<<<(cnt + 127) / 128, 256, 0, s2>>>(
            buf1h + (size_t)off * 128, wt3h, buf3h + (size_t)off * 16, cnt, off);
        cudaEventRecord(ev_h[i], s2);
    }
    for (int i = 0; i < NCHUNK; i++) cudaStreamWaitEvent(0, ev_h[i], 0);

    agg16h_k<<<(n * 4 + 255) / 256, 256>>>(buf3h, b3, out, n);
}